// round 7
// baseline (speedup 1.0000x reference)
#include <cuda_runtime.h>
#include <algorithm>

static constexpr int NB = 8;     // batch
static constexpr int HD = 192;   // hidden dim
#define BN_EPS 1e-5f

// ---------------- scratch (static device memory; no allocations) ----------------
__device__ float g_A[(size_t)NB * HD * 256 * 256];   // 402 MB (res-256 capable)
__device__ float g_Bu[(size_t)NB * HD * 128 * 128];  // 100 MB
__device__ float g_Cu[(size_t)NB * HD * 128 * 128];  // 100 MB
__device__ float g_m0[NB * 256 * 256];
__device__ float g_m1[NB * 128 * 128];
__device__ float g_m2[NB * 64 * 64];
__device__ float g_m3[NB * 32 * 32];
__device__ float g_m4[NB * 16 * 16];
__device__ float g_wt[16 * 192 * 9 * 192];           // transposed conv weights [conv][ic][tap][oc]
__device__ float g_stats[2 * HD];                    // per-channel sum, sumsq
__device__ float g_cnt[5];                           // active-site counts per level
__device__ float g_bn[2 * HD];                       // folded scale, shift

__device__ __forceinline__ float* bufsel(int i) {
    return (i == 0) ? g_A : (i == 1) ? g_Bu : g_Cu;
}
__device__ __forceinline__ float* maskptr(int lvl) {
    switch (lvl) {
        case 0: return g_m0;
        case 1: return g_m1;
        case 2: return g_m2;
        case 3: return g_m3;
        default: return g_m4;
    }
}

// ---------------- packed fp32x2 helpers (Blackwell FFMA2) ----------------
__device__ __forceinline__ void fma2(unsigned long long& d, unsigned long long a, unsigned long long b) {
    asm("fma.rn.f32x2 %0, %1, %2, %0;" : "+l"(d) : "l"(a), "l"(b));
}
__device__ __forceinline__ unsigned long long dup2(float x) {
    unsigned int u = __float_as_uint(x);
    return (unsigned long long)u | ((unsigned long long)u << 32);
}

// ---------------- small utility kernels ----------------
__global__ void k_zcnt() { if (threadIdx.x < 5) g_cnt[threadIdx.x] = 0.f; }
__global__ void k_zstat() { if (threadIdx.x < 2 * HD) g_stats[threadIdx.x] = 0.f; }

// build mask at res 256 from patch mask; accumulate active count
__global__ void k_mask0(const int* __restrict__ mask) {
    int i = blockIdx.x * 256 + threadIdx.x;           // NB*65536 threads
    int b = i >> 16, p = i & 65535;
    int y = p >> 8, x = p & 255;
    float v = 1.f - (float)mask[b * 256 + (y >> 4) * 16 + (x >> 4)];
    g_m0[i] = v;
    float s = v;
    for (int o = 16; o; o >>= 1) s += __shfl_down_sync(0xffffffffu, s, o);
    if ((threadIdx.x & 31) == 0) atomicAdd(&g_cnt[0], s);
}

// mask downsample: k3 s2 p1 max pool; accumulate count for output level
__global__ void k_down(int lvl, int Hin, int Hout) {
    const float* mi = maskptr(lvl - 1);
    float* mo = maskptr(lvl);
    int HW = Hout * Hout;
    int i = blockIdx.x * 256 + threadIdx.x;           // NB*HW threads (multiple of 256)
    int b = i / HW, p = i - b * HW;
    int y = p / Hout, x = p - y * Hout;
    float mx = 0.f;
    #pragma unroll
    for (int dy = 0; dy < 3; dy++) {
        int yy = 2 * y - 1 + dy;
        if (yy < 0 || yy >= Hin) continue;
        #pragma unroll
        for (int dx = 0; dx < 3; dx++) {
            int xx = 2 * x - 1 + dx;
            if (xx < 0 || xx >= Hin) continue;
            mx = fmaxf(mx, mi[(b * Hin + yy) * Hin + xx]);
        }
    }
    mo[i] = mx;
    float s = mx;
    for (int o = 16; o; o >>= 1) s += __shfl_down_sync(0xffffffffu, s, o);
    if ((threadIdx.x & 31) == 0) atomicAdd(&g_cnt[lvl], s);
}

// transpose 16 conv weight tensors OIHW -> [conv][ic][tap][oc]
__global__ void k_wt(const float* __restrict__ dw1, const float* __restrict__ dw2,
                     const float* __restrict__ rw1, const float* __restrict__ rw2) {
    const size_t per = 192 * 9 * 192;                 // 331776
    const size_t total = 16 * per;
    for (size_t i = (size_t)blockIdx.x * blockDim.x + threadIdx.x; i < total;
         i += (size_t)gridDim.x * blockDim.x) {
        int conv = (int)(i / per);
        int r = (int)(i - (size_t)conv * per);
        int ic = r / (9 * 192);
        int r2 = r - ic * (9 * 192);
        int tap = r2 / 192, oc = r2 - tap * 192;
        int layer = conv >> 2, kind = conv & 3;
        const float* src = (kind == 0 ? dw1 : kind == 1 ? dw2 : kind == 2 ? rw1 : rw2)
                           + (size_t)layer * per;
        g_wt[i] = src[(size_t)oc * 1728 + ic * 9 + tap];
    }
}

// stem: 1x1 conv 3 -> 192 at res 256, dense (masking handled by BN)
__global__ void k_stem(const float* __restrict__ img, const float* __restrict__ w) {
    size_t i = (size_t)blockIdx.x * 256 + threadIdx.x; // NB*192*65536 threads
    int p = (int)(i & 65535);
    int oc = (int)((i >> 16) % 192);
    int b = (int)(i / (65536ull * 192));
    const float* ib = img + (size_t)b * 3 * 65536 + p;
    float v = w[oc * 3 + 0] * ib[0] + w[oc * 3 + 1] * ib[65536] + w[oc * 3 + 2] * ib[131072];
    g_A[i] = v;
}

// ---------------- 3x3 conv, 192->192, smem-tiled, f32x2 packed FMA ----------------
// block: 8x8 output pixels, OCPB output channels (192 or 48 slice via blockIdx.z)
// 256 threads = 64 px * 4 oc-groups; weight smem reads are warp-uniform broadcasts.
template <int STRIDE, int OCPB>
__global__ void __launch_bounds__(256, 2)
k_conv3(int srcb, int dstb, int wslot, int Hin, int Hout) {
    constexpr int TP = 8;
    constexpr int IT = (STRIDE == 1) ? (TP + 2) : (2 * TP + 1);
    constexpr int OCT = OCPB / 4;     // oc per thread
    constexpr int NP = OCT / 2;       // packed f32x2 accumulators
    constexpr int ICB = 4;

    const float* in = bufsel(srcb);
    float* out = bufsel(dstb);
    const float* wt = g_wt + (size_t)wslot * (192 * 9 * 192);

    int tilesX = Hout / TP;
    int tx0 = (blockIdx.x % tilesX) * TP;
    int ty0 = (blockIdx.x / tilesX) * TP;
    int b = blockIdx.y;
    int ocb = blockIdx.z * OCPB;
    int t = threadIdx.x;
    int px = t & 63, ocg = t >> 6;
    int lx = px & 7, ly = px >> 3;

    __shared__ __align__(16) float s_w[ICB * 9 * OCPB];
    __shared__ __align__(16) float s_in[ICB * IT * IT];

    unsigned long long acc[NP];
    #pragma unroll
    for (int j = 0; j < NP; j++) acc[j] = 0ull;

    const float* inb = in + (size_t)b * 192 * Hin * Hin;
    int ix0 = tx0 * STRIDE - 1, iy0 = ty0 * STRIDE - 1;

    for (int ic0 = 0; ic0 < 192; ic0 += ICB) {
        __syncthreads();
        // stage weights [icl][tap][oc in block]
        {
            const float* ws = wt + (size_t)ic0 * (9 * 192) + ocb;
            for (int i = t; i < ICB * 9 * OCPB; i += 256) {
                int icl = i / (9 * OCPB);
                int r = i - icl * (9 * OCPB);
                int tap = r / OCPB;
                int j = r - tap * OCPB;
                s_w[i] = ws[icl * (9 * 192) + tap * 192 + j];
            }
        }
        // stage input tile (zero-padded borders)
        for (int i = t; i < ICB * IT * IT; i += 256) {
            int icl = i / (IT * IT);
            int r = i - icl * (IT * IT);
            int rr = r / IT, cc = r - rr * IT;
            int yy = iy0 + rr, xx = ix0 + cc;
            float v = 0.f;
            if (yy >= 0 && yy < Hin && xx >= 0 && xx < Hin)
                v = inb[(size_t)(ic0 + icl) * Hin * Hin + yy * Hin + xx];
            s_in[i] = v;
        }
        __syncthreads();
        #pragma unroll
        for (int icl = 0; icl < ICB; icl++) {
            unsigned long long in2[9];
            #pragma unroll
            for (int dy = 0; dy < 3; dy++)
                #pragma unroll
                for (int dx = 0; dx < 3; dx++)
                    in2[dy * 3 + dx] =
                        dup2(s_in[icl * IT * IT + (ly * STRIDE + dy) * IT + lx * STRIDE + dx]);
            const float* wp = s_w + icl * 9 * OCPB + ocg * OCT;
            #pragma unroll
            for (int tap = 0; tap < 9; tap++) {
                const unsigned long long* w2 =
                    reinterpret_cast<const unsigned long long*>(wp + tap * OCPB);
                #pragma unroll
                for (int j = 0; j < NP; j++) fma2(acc[j], w2[j], in2[tap]);
            }
        }
    }
    int oy = ty0 + ly, ox = tx0 + lx;
    float* ob = out + ((size_t)b * 192 + ocb + ocg * OCT) * Hout * Hout + oy * Hout + ox;
    #pragma unroll
    for (int j = 0; j < NP; j++) {
        float2 f = *reinterpret_cast<float2*>(&acc[j]);
        ob[(size_t)(2 * j) * Hout * Hout] = f.x;
        ob[(size_t)(2 * j + 1) * Hout * Hout] = f.y;
    }
}

// ---------------- masked BN: reduce / finalize / apply ----------------
__global__ void k_reduce(int srcb, int lvl, int HW) {
    const float* x = bufsel(srcb);
    const float* m = maskptr(lvl);
    int c = blockIdx.x;
    int N = NB * HW;
    float s = 0.f, ss = 0.f;
    for (int idx = blockIdx.y * blockDim.x + threadIdx.x; idx < N;
         idx += gridDim.y * blockDim.x) {
        int b = idx / HW, p = idx - b * HW;
        float v = x[((size_t)b * 192 + c) * HW + p] * m[idx];
        s += v;
        ss += v * v;
    }
    for (int o = 16; o; o >>= 1) {
        s += __shfl_down_sync(0xffffffffu, s, o);
        ss += __shfl_down_sync(0xffffffffu, ss, o);
    }
    __shared__ float sh[8][2];
    int w = threadIdx.x >> 5, ln = threadIdx.x & 31;
    if (ln == 0) { sh[w][0] = s; sh[w][1] = ss; }
    __syncthreads();
    if (threadIdx.x == 0) {
        float a = 0.f, b2 = 0.f;
        for (int i = 0; i < 8; i++) { a += sh[i][0]; b2 += sh[i][1]; }
        atomicAdd(&g_stats[c], a);
        atomicAdd(&g_stats[HD + c], b2);
    }
}

__global__ void k_finalize(const float* __restrict__ g, const float* __restrict__ bt, int lvl) {
    int c = threadIdx.x;
    float cnt = fmaxf(g_cnt[lvl], 1.f);
    float mean = g_stats[c] / cnt;
    float var = fmaxf(g_stats[HD + c] / cnt - mean * mean, 0.f);
    float inv = rsqrtf(var + BN_EPS);
    float sc = g[c] * inv;
    g_bn[c] = sc;
    g_bn[HD + c] = bt[c] - mean * sc;
}

// MODE: 0 = plain, 1 = relu, 2 = add-identity + relu
template <int MODE>
__global__ void k_apply(int srcb, int dstb, int idnb, int lvl, int HW, float* extdst) {
    const float* x = bufsel(srcb);
    float* dst = extdst ? extdst : bufsel(dstb);
    const float* idn = bufsel(idnb);
    const float* m = maskptr(lvl);
    int total = NB * 192 * HW;
    for (int i = blockIdx.x * blockDim.x + threadIdx.x; i < total;
         i += gridDim.x * blockDim.x) {
        int bp = i / HW;
        int c = bp % 192;
        int b = bp / 192;
        int p = i - bp * HW;
        float v = (x[i] * g_bn[c] + g_bn[HD + c]) * m[b * HW + p];
        if (MODE == 2) v += idn[i];
        if (MODE >= 1) v = fmaxf(v, 0.f);
        dst[i] = v;
    }
}

// final 1x1 conv 192->192 at res 16 (g_A -> g_Bu)
__global__ void k_fin(const float* __restrict__ w) {
    __shared__ float sx[192];
    int b = blockIdx.x >> 8, p = blockIdx.x & 255;
    int t = threadIdx.x;
    sx[t] = g_A[((size_t)b * 192 + t) * 256 + p];
    __syncthreads();
    const float* wr = w + t * 192;
    float s = 0.f;
    #pragma unroll 8
    for (int ic = 0; ic < 192; ic++) s += __ldg(wr + ic) * sx[ic];
    g_Bu[((size_t)b * 192 + t) * 256 + p] = s;
}

// auxiliary outputs: mask (as float) and ids_restore
__global__ void k_aux(const int* __restrict__ mask, float* __restrict__ out) {
    int i = blockIdx.x * 256 + threadIdx.x;
    if (i < 2048) {
        out[393216 + i] = (float)mask[i];
        out[395264 + i] = (float)(i & 255);
    }
}

// ---------------- host orchestration ----------------
extern "C" void kernel_launch(void* const* d_in, const int* in_sizes, int n_in,
                              void* d_out, int out_size) {
    const float* images = (const float*)d_in[0];
    const int* mask = (const int*)d_in[1];
    const float* stem_w = (const float*)d_in[2];
    const float* stem_g = (const float*)d_in[3];
    const float* stem_b = (const float*)d_in[4];
    const float* dw1 = (const float*)d_in[5];
    const float* dg1 = (const float*)d_in[6];
    const float* db1 = (const float*)d_in[7];
    const float* dw2 = (const float*)d_in[8];
    const float* dg2 = (const float*)d_in[9];
    const float* db2 = (const float*)d_in[10];
    const float* rw1 = (const float*)d_in[11];
    const float* rg1 = (const float*)d_in[12];
    const float* rb1 = (const float*)d_in[13];
    const float* rw2 = (const float*)d_in[14];
    const float* rg2 = (const float*)d_in[15];
    const float* rb2 = (const float*)d_in[16];
    const float* fw = (const float*)d_in[17];
    const float* fg = (const float*)d_in[18];
    const float* fb = (const float*)d_in[19];
    float* out = (float*)d_out;

    // masks + counts
    k_zcnt<<<1, 32>>>();
    k_mask0<<<NB * 65536 / 256, 256>>>(mask);
    k_down<<<NB * 128 * 128 / 256, 256>>>(1, 256, 128);
    k_down<<<NB * 64 * 64 / 256, 256>>>(2, 128, 64);
    k_down<<<NB * 32 * 32 / 256, 256>>>(3, 64, 32);
    k_down<<<NB * 16 * 16 / 256, 256>>>(4, 32, 16);
    // transposed weights
    k_wt<<<8192, 256>>>(dw1, dw2, rw1, rw2);
    // stem conv into A
    k_stem<<<NB * 192 * 65536 / 256, 256>>>(images, stem_w);

    auto BN = [&](int srcb, int dstb, int idnb, int lvl, int HW,
                  const float* g, const float* bt, int mode, float* ext) {
        k_zstat<<<1, 2 * HD>>>();
        int ny = std::max(1, std::min(64, (NB * HW) / 8192));
        k_reduce<<<dim3(192, ny), 256>>>(srcb, lvl, HW);
        k_finalize<<<1, 192>>>(g, bt, lvl);
        int total = NB * 192 * HW;
        int blocks = std::min(8192, (total + 255) / 256);
        if (mode == 0)      k_apply<0><<<blocks, 256>>>(srcb, dstb, 0, lvl, HW, ext);
        else if (mode == 1) k_apply<1><<<blocks, 256>>>(srcb, dstb, 0, lvl, HW, ext);
        else                k_apply<2><<<blocks, 256>>>(srcb, dstb, idnb, lvl, HW, ext);
    };
    auto CONV = [&](int stride, int srcb, int dstb, int slot, int Hin_, int Hout_) {
        dim3 grid((Hout_ / 8) * (Hout_ / 8), NB, 1);
        if (Hout_ >= 64) {
            if (stride == 2) k_conv3<2, 192><<<grid, 256>>>(srcb, dstb, slot, Hin_, Hout_);
            else             k_conv3<1, 192><<<grid, 256>>>(srcb, dstb, slot, Hin_, Hout_);
        } else {
            grid.z = 4;
            if (stride == 2) k_conv3<2, 48><<<grid, 256>>>(srcb, dstb, slot, Hin_, Hout_);
            else             k_conv3<1, 48><<<grid, 256>>>(srcb, dstb, slot, Hin_, Hout_);
        }
    };

    // stem BN + ReLU (in place in A, level 0)
    BN(0, 0, 0, 0, 65536, stem_g, stem_b, 1, nullptr);

    int Hin = 256;
    for (int i = 0; i < 4; i++) {
        int Hout = Hin / 2;
        int HW = Hout * Hout;
        int lvl = i + 1;
        // downsample conv d1 (stride 2): A -> B, BN+ReLU in place
        CONV(2, 0, 1, i * 4 + 0, Hin, Hout);
        BN(1, 1, 0, lvl, HW, dg1 + i * 192, db1 + i * 192, 1, nullptr);
        // subm conv d2: B -> C, BN (no relu) -> A  (A becomes block output / identity)
        CONV(1, 1, 2, i * 4 + 1, Hout, Hout);
        BN(2, 0, 0, lvl, HW, dg2 + i * 192, db2 + i * 192, 0, nullptr);
        // residual branch: r1: A -> B, BN+ReLU in place
        CONV(1, 0, 1, i * 4 + 2, Hout, Hout);
        BN(1, 1, 0, lvl, HW, rg1 + i * 192, rb1 + i * 192, 1, nullptr);
        // r2: B -> C, BN + add identity(A) + ReLU -> A
        CONV(1, 1, 2, i * 4 + 3, Hout, Hout);
        BN(2, 0, 0, lvl, HW, rg2 + i * 192, rb2 + i * 192, 2, nullptr);
        Hin = Hout;
    }

    // final 1x1 proj: A@16 -> B, then BN + ReLU straight into d_out
    k_fin<<<NB * 256, 192>>>(fw);
    BN(1, 1, 0, 4, 256, fg, fb, 1, out);

    // aux outputs (mask + ids_restore) if the harness expects the full tuple
    if (out_size >= 397312) k_aux<<<8, 256>>>(mask, out);
}

// round 8
// speedup vs baseline: 1.2080x; 1.2080x over previous
#include <cuda_runtime.h>
#include <algorithm>

static constexpr int NB = 8;     // batch
static constexpr int HD = 192;   // hidden dim
#define BN_EPS 1e-5f

typedef unsigned long long u64;

// ---------------- scratch (static device memory; no allocations) ----------------
__device__ float g_A[(size_t)NB * HD * 256 * 256];   // 402 MB (res-256 capable)
__device__ float g_Bu[(size_t)NB * HD * 128 * 128];  // 100 MB
__device__ float g_Cu[(size_t)NB * HD * 128 * 128];  // 100 MB
__device__ float g_m0[NB * 256 * 256];
__device__ float g_m1[NB * 128 * 128];
__device__ float g_m2[NB * 64 * 64];
__device__ float g_m3[NB * 32 * 32];
__device__ float g_m4[NB * 16 * 16];
__device__ float g_wt[16 * 192 * 9 * 192];           // transposed conv weights [conv][ic][tap][oc]
__device__ float g_stats[2 * HD];                    // per-channel sum, sumsq (reused serially)
__device__ float g_cnt[5];                           // active-site counts per level
__device__ float g_bn2[18 * 2 * HD];                 // folded BN params per instance (18 slots)

__device__ __forceinline__ float* bufsel(int i) {
    return (i == 0) ? g_A : (i == 1) ? g_Bu : g_Cu;
}
__device__ __forceinline__ float* maskptr(int lvl) {
    switch (lvl) {
        case 0: return g_m0;
        case 1: return g_m1;
        case 2: return g_m2;
        case 3: return g_m3;
        default: return g_m4;
    }
}

// ---------------- packed fp32x2 helpers (Blackwell FFMA2) ----------------
__device__ __forceinline__ void fma2(u64& d, u64 a, u64 b) {
    asm("fma.rn.f32x2 %0, %1, %2, %0;" : "+l"(d) : "l"(a), "l"(b));
}
__device__ __forceinline__ u64 mul2(u64 a, u64 b) {
    u64 d; asm("mul.rn.f32x2 %0, %1, %2;" : "=l"(d) : "l"(a), "l"(b)); return d;
}
__device__ __forceinline__ u64 add2(u64 a, u64 b) {
    u64 d; asm("add.rn.f32x2 %0, %1, %2;" : "=l"(d) : "l"(a), "l"(b)); return d;
}
__device__ __forceinline__ u64 dup2(float x) {
    unsigned int u = __float_as_uint(x);
    return (u64)u | ((u64)u << 32);
}
__device__ __forceinline__ float2 up2(u64 v) {
    float2 f;
    f.x = __uint_as_float((unsigned int)v);
    f.y = __uint_as_float((unsigned int)(v >> 32));
    return f;
}

// ---------------- small utility kernels ----------------
__global__ void k_zcnt() { if (threadIdx.x < 5) g_cnt[threadIdx.x] = 0.f; }
__global__ void k_zstat() { if (threadIdx.x < 2 * HD) g_stats[threadIdx.x] = 0.f; }

// build mask at res 256 from patch mask; accumulate active count
__global__ void k_mask0(const int* __restrict__ mask) {
    int i = blockIdx.x * 256 + threadIdx.x;
    int b = i >> 16, p = i & 65535;
    int y = p >> 8, x = p & 255;
    float v = 1.f - (float)mask[b * 256 + (y >> 4) * 16 + (x >> 4)];
    g_m0[i] = v;
    float s = v;
    for (int o = 16; o; o >>= 1) s += __shfl_down_sync(0xffffffffu, s, o);
    if ((threadIdx.x & 31) == 0) atomicAdd(&g_cnt[0], s);
}

// mask downsample: k3 s2 p1 max pool; accumulate count for output level
__global__ void k_down(int lvl, int Hin, int Hout) {
    const float* mi = maskptr(lvl - 1);
    float* mo = maskptr(lvl);
    int HW = Hout * Hout;
    int i = blockIdx.x * 256 + threadIdx.x;
    int b = i / HW, p = i - b * HW;
    int y = p / Hout, x = p - y * Hout;
    float mx = 0.f;
    #pragma unroll
    for (int dy = 0; dy < 3; dy++) {
        int yy = 2 * y - 1 + dy;
        if (yy < 0 || yy >= Hin) continue;
        #pragma unroll
        for (int dx = 0; dx < 3; dx++) {
            int xx = 2 * x - 1 + dx;
            if (xx < 0 || xx >= Hin) continue;
            mx = fmaxf(mx, mi[(b * Hin + yy) * Hin + xx]);
        }
    }
    mo[i] = mx;
    float s = mx;
    for (int o = 16; o; o >>= 1) s += __shfl_down_sync(0xffffffffu, s, o);
    if ((threadIdx.x & 31) == 0) atomicAdd(&g_cnt[lvl], s);
}

// transpose 16 conv weight tensors OIHW -> [conv][ic][tap][oc]
__global__ void k_wt(const float* __restrict__ dw1, const float* __restrict__ dw2,
                     const float* __restrict__ rw1, const float* __restrict__ rw2) {
    const size_t per = 192 * 9 * 192;
    const size_t total = 16 * per;
    for (size_t i = (size_t)blockIdx.x * blockDim.x + threadIdx.x; i < total;
         i += (size_t)gridDim.x * blockDim.x) {
        int conv = (int)(i / per);
        int r = (int)(i - (size_t)conv * per);
        int ic = r / (9 * 192);
        int r2 = r - ic * (9 * 192);
        int tap = r2 / 192, oc = r2 - tap * 192;
        int layer = conv >> 2, kind = conv & 3;
        const float* src = (kind == 0 ? dw1 : kind == 1 ? dw2 : kind == 2 ? rw1 : rw2)
                           + (size_t)layer * per;
        g_wt[i] = src[(size_t)oc * 1728 + ic * 9 + tap];
    }
}

// stem: 1x1 conv 3 -> 192 at res 256, raw output + fused masked BN stats
__global__ void k_stem(const float* __restrict__ img, const float* __restrict__ w) {
    size_t i = (size_t)blockIdx.x * 256 + threadIdx.x;
    int p = (int)(i & 65535);
    int oc = (int)((i >> 16) % 192);
    int b = (int)(i / (65536ull * 192));
    const float* ib = img + (size_t)b * 3 * 65536 + p;
    float v = w[oc * 3 + 0] * ib[0] + w[oc * 3 + 1] * ib[65536] + w[oc * 3 + 2] * ib[131072];
    g_A[i] = v;
    float m = g_m0[b * 65536 + p];
    float s = v * m, q = v * v * m;
    for (int o = 16; o; o >>= 1) {
        s += __shfl_down_sync(0xffffffffu, s, o);
        q += __shfl_down_sync(0xffffffffu, q, o);
    }
    __shared__ float sh[8][2];
    int wrp = threadIdx.x >> 5, ln = threadIdx.x & 31;
    if (ln == 0) { sh[wrp][0] = s; sh[wrp][1] = q; }
    __syncthreads();
    if (threadIdx.x == 0) {
        float a = 0.f, b2 = 0.f;
        #pragma unroll
        for (int k = 0; k < 8; k++) { a += sh[k][0]; b2 += sh[k][1]; }
        atomicAdd(&g_stats[oc], a);
        atomicAdd(&g_stats[HD + oc], b2);
    }
}

// ================= 3x3 conv 192->192, register-tiled, dup'd-smem, fused =================
// block: 16x16 output px, 64 oc slice (blockIdx.z); 256 threads = 64 px-groups(2x2) x 4 oc-groups(16 oc)
// staging applies BN(inslot)+mask+optional relu of the INPUT tensor;
// epilogue writes raw conv output + accumulates masked BN stats into g_stats.
template <int STRIDE, int ICB>
__global__ void __launch_bounds__(256, 2)
k_conv3(int srcb, int dstb, int wslot, int Hin, int Hout,
        int inslot, int inlvl, int inrelu, int outlvl) {
    constexpr int IT = 15 * STRIDE + 3;   // stride1:18, stride2:33
    constexpr int OCPB = 64;
    constexpr int PSX = STRIDE + 3;

    __shared__ __align__(16) u64 s_in[ICB * IT * IT];
    __shared__ __align__(16) float s_w[ICB * 9 * OCPB];

    const float* in = bufsel(srcb);
    float* out = bufsel(dstb);
    const float* wt = g_wt + (size_t)wslot * (192 * 9 * 192);

    int tiles = Hout >> 4;
    int tx0 = (blockIdx.x % tiles) << 4;
    int ty0 = (blockIdx.x / tiles) << 4;
    int b = blockIdx.y;
    int ocb = blockIdx.z * OCPB;
    int t = threadIdx.x;
    int ocg = t >> 6;
    int pxg = t & 63, gx = pxg & 7, gy = pxg >> 3;

    const float* mski = (inslot >= 0) ? maskptr(inlvl) + (size_t)b * Hin * Hin : nullptr;
    const float* bnin = (inslot >= 0) ? g_bn2 + inslot * 384 : nullptr;

    u64 acc[2][2][8];
    #pragma unroll
    for (int py = 0; py < 2; py++)
        #pragma unroll
        for (int px = 0; px < 2; px++)
            #pragma unroll
            for (int j = 0; j < 8; j++) acc[py][px][j] = 0ull;

    const float* inb = in + (size_t)b * 192 * Hin * Hin;
    int ix0 = tx0 * STRIDE - 1, iy0 = ty0 * STRIDE - 1;

    for (int ic0 = 0; ic0 < 192; ic0 += ICB) {
        __syncthreads();
        // stage weights [icl][tap][oc]
        for (int i = t; i < ICB * 9 * OCPB; i += 256) {
            int icl = i / (9 * OCPB);
            int r = i - icl * (9 * OCPB);
            int tap = r >> 6, j = r & 63;
            s_w[i] = wt[(size_t)(ic0 + icl) * (9 * 192) + tap * 192 + ocb + j];
        }
        // stage input tile, duplicated as f32x2, with fused BN/mask/relu transform
        for (int i = t; i < ICB * IT * IT; i += 256) {
            int icl = i / (IT * IT);
            int r = i - icl * (IT * IT);
            int rr = r / IT, cc = r - rr * IT;
            int yy = iy0 + rr, xx = ix0 + cc;
            float v = 0.f;
            if ((unsigned)yy < (unsigned)Hin && (unsigned)xx < (unsigned)Hin) {
                v = inb[(size_t)(ic0 + icl) * Hin * Hin + yy * Hin + xx];
                if (inslot >= 0) {
                    int c = ic0 + icl;
                    v = (v * bnin[c] + bnin[192 + c]) * mski[yy * Hin + xx];
                    if (inrelu) v = fmaxf(v, 0.f);
                }
            }
            s_in[i] = dup2(v);
        }
        __syncthreads();
        #pragma unroll
        for (int icl = 0; icl < ICB; icl++) {
            const u64* ip = s_in + icl * IT * IT + (gy * 2 * STRIDE) * IT + gx * 2 * STRIDE;
            const float* wp = s_w + icl * 9 * OCPB + ocg * 16;
            #pragma unroll
            for (int dy = 0; dy < 3; dy++) {
                u64 r0[PSX], r1[PSX];
                #pragma unroll
                for (int c = 0; c < PSX; c++) {
                    r0[c] = ip[dy * IT + c];
                    r1[c] = ip[(STRIDE + dy) * IT + c];
                }
                #pragma unroll
                for (int dx = 0; dx < 3; dx++) {
                    const u64* wv = reinterpret_cast<const u64*>(wp + (dy * 3 + dx) * OCPB);
                    u64 w2[8];
                    #pragma unroll
                    for (int j = 0; j < 8; j++) w2[j] = wv[j];
                    #pragma unroll
                    for (int j = 0; j < 8; j++) {
                        fma2(acc[0][0][j], w2[j], r0[dx]);
                        fma2(acc[0][1][j], w2[j], r0[STRIDE + dx]);
                        fma2(acc[1][0][j], w2[j], r1[dx]);
                        fma2(acc[1][1][j], w2[j], r1[STRIDE + dx]);
                    }
                }
            }
        }
    }

    // epilogue: masked BN stats (packed) + raw output write
    int oy0 = ty0 + gy * 2, ox0 = tx0 + gx * 2;
    int HWo = Hout * Hout;
    const float* mo = maskptr(outlvl) + (size_t)b * HWo;
    float m00 = mo[oy0 * Hout + ox0], m01 = mo[oy0 * Hout + ox0 + 1];
    float m10 = mo[(oy0 + 1) * Hout + ox0], m11 = mo[(oy0 + 1) * Hout + ox0 + 1];
    u64 dm[2][2] = {{dup2(m00), dup2(m01)}, {dup2(m10), dup2(m11)}};
    u64 sum[8], ss[8];
    #pragma unroll
    for (int j = 0; j < 8; j++) {
        sum[j] = 0ull; ss[j] = 0ull;
        #pragma unroll
        for (int py = 0; py < 2; py++)
            #pragma unroll
            for (int px = 0; px < 2; px++) {
                fma2(sum[j], acc[py][px][j], dm[py][px]);
                u64 sq = mul2(acc[py][px][j], acc[py][px][j]);
                fma2(ss[j], sq, dm[py][px]);
            }
    }
    #pragma unroll
    for (int o = 16; o; o >>= 1) {
        #pragma unroll
        for (int j = 0; j < 8; j++) {
            sum[j] = add2(sum[j], __shfl_down_sync(0xffffffffu, sum[j], o));
            ss[j] = add2(ss[j], __shfl_down_sync(0xffffffffu, ss[j], o));
        }
    }
    if ((t & 31) == 0) {
        int oc0 = ocb + ocg * 16;
        #pragma unroll
        for (int j = 0; j < 8; j++) {
            float2 s = up2(sum[j]), q = up2(ss[j]);
            atomicAdd(&g_stats[oc0 + 2 * j], s.x);
            atomicAdd(&g_stats[oc0 + 2 * j + 1], s.y);
            atomicAdd(&g_stats[HD + oc0 + 2 * j], q.x);
            atomicAdd(&g_stats[HD + oc0 + 2 * j + 1], q.y);
        }
    }
    float* ob = out + ((size_t)b * 192 + ocb + ocg * 16) * HWo;
    #pragma unroll
    for (int j = 0; j < 8; j++) {
        float2 p00 = up2(acc[0][0][j]), p01 = up2(acc[0][1][j]);
        float2 p10 = up2(acc[1][0][j]), p11 = up2(acc[1][1][j]);
        float* c0 = ob + (size_t)(2 * j) * HWo + oy0 * Hout + ox0;
        float* c1 = ob + (size_t)(2 * j + 1) * HWo + oy0 * Hout + ox0;
        *(float2*)c0 = make_float2(p00.x, p01.x);
        *(float2*)(c0 + Hout) = make_float2(p10.x, p11.x);
        *(float2*)c1 = make_float2(p00.y, p01.y);
        *(float2*)(c1 + Hout) = make_float2(p10.y, p11.y);
    }
}

// ---------------- BN finalize: fold gamma/beta into per-slot scale/shift ----------------
__global__ void k_finalize(int slot, const float* __restrict__ g,
                           const float* __restrict__ bt, int lvl) {
    int c = threadIdx.x;
    float cnt = fmaxf(g_cnt[lvl], 1.f);
    float mean = g_stats[c] / cnt;
    float var = fmaxf(g_stats[HD + c] / cnt - mean * mean, 0.f);
    float inv = rsqrtf(var + BN_EPS);
    float sc = g[c] * inv;
    g_bn2[slot * 384 + c] = sc;
    g_bn2[slot * 384 + HD + c] = bt[c] - mean * sc;
}

// final apply: BN + mask + relu -> external out
__global__ void k_apply1(int srcb, int slot, int lvl, int HW, float* __restrict__ dst) {
    const float* x = bufsel(srcb);
    const float* m = maskptr(lvl);
    const float* bn = g_bn2 + slot * 384;
    int total = NB * 192 * HW;
    for (int i = blockIdx.x * blockDim.x + threadIdx.x; i < total;
         i += gridDim.x * blockDim.x) {
        int bp = i / HW;
        int c = bp % 192, b = bp / 192;
        int p = i - bp * HW;
        float v = (x[i] * bn[c] + bn[192 + c]) * m[b * HW + p];
        dst[i] = fmaxf(v, 0.f);
    }
}

// residual combine: relu( bn_a(x)*m + bn_b(idn)*m ) -> dst buffer
__global__ void k_apply2(int srcb, int sa, int idnb, int sb, int dstb, int lvl, int HW) {
    const float* x = bufsel(srcb);
    const float* idn = bufsel(idnb);
    float* dst = bufsel(dstb);
    const float* m = maskptr(lvl);
    const float* bna = g_bn2 + sa * 384;
    const float* bnb = g_bn2 + sb * 384;
    int total = NB * 192 * HW;
    for (int i = blockIdx.x * blockDim.x + threadIdx.x; i < total;
         i += gridDim.x * blockDim.x) {
        int bp = i / HW;
        int c = bp % 192, b = bp / 192;
        int p = i - bp * HW;
        float mm = m[b * HW + p];
        float v = (x[i] * bna[c] + bna[192 + c]) * mm;
        float w = (idn[i] * bnb[c] + bnb[192 + c]) * mm;
        dst[i] = fmaxf(v + w, 0.f);
    }
}

// final 1x1 conv 192->192 at res 16 (g_A -> g_Bu), fused masked stats
__global__ void k_fin(const float* __restrict__ w) {
    __shared__ float sx[192];
    int b = blockIdx.x >> 8, p = blockIdx.x & 255;
    int t = threadIdx.x;
    sx[t] = g_A[((size_t)b * 192 + t) * 256 + p];
    __syncthreads();
    const float* wr = w + t * 192;
    float s = 0.f;
    #pragma unroll 8
    for (int ic = 0; ic < 192; ic++) s += __ldg(wr + ic) * sx[ic];
    g_Bu[((size_t)b * 192 + t) * 256 + p] = s;
    float m = g_m4[b * 256 + p];
    atomicAdd(&g_stats[t], s * m);
    atomicAdd(&g_stats[HD + t], s * s * m);
}

// auxiliary outputs: mask (as float) and ids_restore
__global__ void k_aux(const int* __restrict__ mask, float* __restrict__ out) {
    int i = blockIdx.x * 256 + threadIdx.x;
    if (i < 2048) {
        out[393216 + i] = (float)mask[i];
        out[395264 + i] = (float)(i & 255);
    }
}

// ---------------- host orchestration ----------------
extern "C" void kernel_launch(void* const* d_in, const int* in_sizes, int n_in,
                              void* d_out, int out_size) {
    const float* images = (const float*)d_in[0];
    const int* mask = (const int*)d_in[1];
    const float* stem_w = (const float*)d_in[2];
    const float* stem_g = (const float*)d_in[3];
    const float* stem_b = (const float*)d_in[4];
    const float* dw1 = (const float*)d_in[5];
    const float* dg1 = (const float*)d_in[6];
    const float* db1 = (const float*)d_in[7];
    const float* dw2 = (const float*)d_in[8];
    const float* dg2 = (const float*)d_in[9];
    const float* db2 = (const float*)d_in[10];
    const float* rw1 = (const float*)d_in[11];
    const float* rg1 = (const float*)d_in[12];
    const float* rb1 = (const float*)d_in[13];
    const float* rw2 = (const float*)d_in[14];
    const float* rg2 = (const float*)d_in[15];
    const float* rb2 = (const float*)d_in[16];
    const float* fw = (const float*)d_in[17];
    const float* fg = (const float*)d_in[18];
    const float* fb = (const float*)d_in[19];
    float* out = (float*)d_out;

    // masks + counts
    k_zcnt<<<1, 32>>>();
    k_mask0<<<NB * 65536 / 256, 256>>>(mask);
    k_down<<<NB * 128 * 128 / 256, 256>>>(1, 256, 128);
    k_down<<<NB * 64 * 64 / 256, 256>>>(2, 128, 64);
    k_down<<<NB * 32 * 32 / 256, 256>>>(3, 64, 32);
    k_down<<<NB * 16 * 16 / 256, 256>>>(4, 32, 16);
    // transposed weights
    k_wt<<<8192, 256>>>(dw1, dw2, rw1, rw2);

    // stem conv (raw into A) with fused stats; finalize BN slot 0
    k_zstat<<<1, 2 * HD>>>();
    k_stem<<<NB * 192 * 65536 / 256, 256>>>(images, stem_w);
    k_finalize<<<1, 192>>>(0, stem_g, stem_b, 0);

    int Hin = 256;
    for (int i = 0; i < 4; i++) {
        int Hout = Hin / 2;
        int HW = Hout * Hout;
        int lvl = i + 1;
        int tiles = Hout / 16;
        dim3 cgrid(tiles * tiles, NB, 3);

        // d1 (stride 2): A(raw + slot-in transform) -> B raw, stats -> slot 4i+1
        k_zstat<<<1, 2 * HD>>>();
        k_conv3<2, 4><<<cgrid, 256>>>(0, 1, 4 * i + 0, Hin, Hout,
                                      (i == 0 ? 0 : -1), lvl - 1, (i == 0 ? 1 : 0), lvl);
        k_finalize<<<1, 192>>>(4 * i + 1, dg1 + i * 192, db1 + i * 192, lvl);

        // d2: B (slot d1, relu) -> C raw, stats -> slot 4i+2
        k_zstat<<<1, 2 * HD>>>();
        k_conv3<1, 8><<<cgrid, 256>>>(1, 2, 4 * i + 1, Hout, Hout,
                                      4 * i + 1, lvl, 1, lvl);
        k_finalize<<<1, 192>>>(4 * i + 2, dg2 + i * 192, db2 + i * 192, lvl);

        // r1: C (slot d2, NO relu) -> B raw, stats -> slot 4i+3
        k_zstat<<<1, 2 * HD>>>();
        k_conv3<1, 8><<<cgrid, 256>>>(2, 1, 4 * i + 2, Hout, Hout,
                                      4 * i + 2, lvl, 0, lvl);
        k_finalize<<<1, 192>>>(4 * i + 3, rg1 + i * 192, rb1 + i * 192, lvl);

        // r2: B (slot r1, relu) -> A raw, stats -> slot 4i+4
        k_zstat<<<1, 2 * HD>>>();
        k_conv3<1, 8><<<cgrid, 256>>>(1, 0, 4 * i + 3, Hout, Hout,
                                      4 * i + 3, lvl, 1, lvl);
        k_finalize<<<1, 192>>>(4 * i + 4, rg2 + i * 192, rb2 + i * 192, lvl);

        // residual combine: relu(bn_{r2}(A)*m + bn_{d2}(C)*m) -> A (materialized x)
        int blocks = std::min(8192, (NB * 192 * HW + 255) / 256);
        k_apply2<<<blocks, 256>>>(0, 4 * i + 4, 2, 4 * i + 2, 0, lvl, HW);
        Hin = Hout;
    }

    // final 1x1 proj: A@16 -> B raw (fused stats), finalize slot 17, apply -> out
    k_zstat<<<1, 2 * HD>>>();
    k_fin<<<NB * 256, 192>>>(fw);
    k_finalize<<<1, 192>>>(17, fg, fb, 4);
    k_apply1<<<1536, 256>>>(1, 17, 4, 256, out);

    // aux outputs (mask + ids_restore) if the harness expects the full tuple
    if (out_size >= 397312) k_aux<<<8, 256>>>(mask, out);
}

// round 9
// speedup vs baseline: 1.2586x; 1.0419x over previous
#include <cuda_runtime.h>
#include <algorithm>

static constexpr int NB = 8;     // batch
static constexpr int HD = 192;   // hidden dim
#define BN_EPS 1e-5f

typedef unsigned long long u64;

// ---------------- scratch (static device memory; no allocations) ----------------
__device__ float g_A[(size_t)NB * HD * 256 * 256];   // 402 MB (res-256 capable)
__device__ float g_Bu[(size_t)NB * HD * 128 * 128];  // 100 MB
__device__ float g_Cu[(size_t)NB * HD * 128 * 128];  // 100 MB
__device__ float g_m0[NB * 256 * 256];
__device__ float g_m1[NB * 128 * 128];
__device__ float g_m2[NB * 64 * 64];
__device__ float g_m3[NB * 32 * 32];
__device__ float g_m4[NB * 16 * 16];
__device__ float g_wt[16 * 192 * 9 * 192];           // transposed conv weights [conv][ic][tap][oc]
__device__ float g_stats[2 * HD];                    // per-channel sum, sumsq (reused serially)
__device__ float g_cnt[5];                           // active-site counts per level
__device__ float g_bn2[18 * 2 * HD];                 // folded BN params per instance (18 slots)

__device__ __forceinline__ float* bufsel(int i) {
    return (i == 0) ? g_A : (i == 1) ? g_Bu : g_Cu;
}
__device__ __forceinline__ float* maskptr(int lvl) {
    switch (lvl) {
        case 0: return g_m0;
        case 1: return g_m1;
        case 2: return g_m2;
        case 3: return g_m3;
        default: return g_m4;
    }
}

// ---------------- packed fp32x2 helpers (Blackwell FFMA2) ----------------
__device__ __forceinline__ void fma2(u64& d, u64 a, u64 b) {
    asm("fma.rn.f32x2 %0, %1, %2, %0;" : "+l"(d) : "l"(a), "l"(b));
}
__device__ __forceinline__ u64 mul2(u64 a, u64 b) {
    u64 d; asm("mul.rn.f32x2 %0, %1, %2;" : "=l"(d) : "l"(a), "l"(b)); return d;
}
__device__ __forceinline__ u64 add2(u64 a, u64 b) {
    u64 d; asm("add.rn.f32x2 %0, %1, %2;" : "=l"(d) : "l"(a), "l"(b)); return d;
}
__device__ __forceinline__ u64 dup2(float x) {
    unsigned int u = __float_as_uint(x);
    return (u64)u | ((u64)u << 32);
}
__device__ __forceinline__ float2 up2(u64 v) {
    float2 f;
    f.x = __uint_as_float((unsigned int)v);
    f.y = __uint_as_float((unsigned int)(v >> 32));
    return f;
}

// ---------------- small utility kernels ----------------
__global__ void k_zcnt() { if (threadIdx.x < 5) g_cnt[threadIdx.x] = 0.f; }
__global__ void k_zstat() { if (threadIdx.x < 2 * HD) g_stats[threadIdx.x] = 0.f; }

// build mask at res 256 from patch mask; accumulate active count
__global__ void k_mask0(const int* __restrict__ mask) {
    int i = blockIdx.x * 256 + threadIdx.x;
    int b = i >> 16, p = i & 65535;
    int y = p >> 8, x = p & 255;
    float v = 1.f - (float)mask[b * 256 + (y >> 4) * 16 + (x >> 4)];
    g_m0[i] = v;
    float s = v;
    for (int o = 16; o; o >>= 1) s += __shfl_down_sync(0xffffffffu, s, o);
    if ((threadIdx.x & 31) == 0) atomicAdd(&g_cnt[0], s);
}

// mask downsample: k3 s2 p1 max pool; accumulate count for output level
__global__ void k_down(int lvl, int Hin, int Hout) {
    const float* mi = maskptr(lvl - 1);
    float* mo = maskptr(lvl);
    int HW = Hout * Hout;
    int i = blockIdx.x * 256 + threadIdx.x;
    int b = i / HW, p = i - b * HW;
    int y = p / Hout, x = p - y * Hout;
    float mx = 0.f;
    #pragma unroll
    for (int dy = 0; dy < 3; dy++) {
        int yy = 2 * y - 1 + dy;
        if (yy < 0 || yy >= Hin) continue;
        #pragma unroll
        for (int dx = 0; dx < 3; dx++) {
            int xx = 2 * x - 1 + dx;
            if (xx < 0 || xx >= Hin) continue;
            mx = fmaxf(mx, mi[(b * Hin + yy) * Hin + xx]);
        }
    }
    mo[i] = mx;
    float s = mx;
    for (int o = 16; o; o >>= 1) s += __shfl_down_sync(0xffffffffu, s, o);
    if ((threadIdx.x & 31) == 0) atomicAdd(&g_cnt[lvl], s);
}

// transpose 16 conv weight tensors OIHW -> [conv][ic][tap][oc]
__global__ void k_wt(const float* __restrict__ dw1, const float* __restrict__ dw2,
                     const float* __restrict__ rw1, const float* __restrict__ rw2) {
    const size_t per = 192 * 9 * 192;
    const size_t total = 16 * per;
    for (size_t i = (size_t)blockIdx.x * blockDim.x + threadIdx.x; i < total;
         i += (size_t)gridDim.x * blockDim.x) {
        int conv = (int)(i / per);
        int r = (int)(i - (size_t)conv * per);
        int ic = r / (9 * 192);
        int r2 = r - ic * (9 * 192);
        int tap = r2 / 192, oc = r2 - tap * 192;
        int layer = conv >> 2, kind = conv & 3;
        const float* src = (kind == 0 ? dw1 : kind == 1 ? dw2 : kind == 2 ? rw1 : rw2)
                           + (size_t)layer * per;
        g_wt[i] = src[(size_t)oc * 1728 + ic * 9 + tap];
    }
}

// stem: 1x1 conv 3 -> 192 at res 256, raw output + fused masked BN stats
__global__ void k_stem(const float* __restrict__ img, const float* __restrict__ w) {
    size_t i = (size_t)blockIdx.x * 256 + threadIdx.x;
    int p = (int)(i & 65535);
    int oc = (int)((i >> 16) % 192);
    int b = (int)(i / (65536ull * 192));
    const float* ib = img + (size_t)b * 3 * 65536 + p;
    float v = w[oc * 3 + 0] * ib[0] + w[oc * 3 + 1] * ib[65536] + w[oc * 3 + 2] * ib[131072];
    g_A[i] = v;
    float m = g_m0[b * 65536 + p];
    float s = v * m, q = v * v * m;
    for (int o = 16; o; o >>= 1) {
        s += __shfl_down_sync(0xffffffffu, s, o);
        q += __shfl_down_sync(0xffffffffu, q, o);
    }
    __shared__ float sh[8][2];
    int wrp = threadIdx.x >> 5, ln = threadIdx.x & 31;
    if (ln == 0) { sh[wrp][0] = s; sh[wrp][1] = q; }
    __syncthreads();
    if (threadIdx.x == 0) {
        float a = 0.f, b2 = 0.f;
        #pragma unroll
        for (int k = 0; k < 8; k++) { a += sh[k][0]; b2 += sh[k][1]; }
        atomicAdd(&g_stats[oc], a);
        atomicAdd(&g_stats[HD + oc], b2);
    }
}

// ================= 3x3 conv 192->192, register-tiled, dup'd-smem, fused =================
// block: 16x16 output px, 64 oc slice (blockIdx.z); 256 threads = 64 px-groups(2x2) x 4 oc-groups(16 oc)
// staging applies BN(inslot)+mask+optional relu of the INPUT tensor;
// epilogue writes raw conv output + accumulates masked BN stats into g_stats.
template <int STRIDE, int ICB>
__global__ void __launch_bounds__(256, 2)
k_conv3(int srcb, int dstb, int wslot, int Hin, int Hout,
        int inslot, int inlvl, int inrelu, int outlvl) {
    constexpr int IT = 15 * STRIDE + 3;   // stride1:18, stride2:33
    constexpr int OCPB = 64;
    constexpr int PSX = STRIDE + 3;

    __shared__ __align__(16) u64 s_in[ICB * IT * IT];
    __shared__ __align__(16) float s_w[ICB * 9 * OCPB];

    const float* in = bufsel(srcb);
    float* out = bufsel(dstb);
    const float* wt = g_wt + (size_t)wslot * (192 * 9 * 192);

    int tiles = Hout >> 4;
    int tx0 = (blockIdx.x % tiles) << 4;
    int ty0 = (blockIdx.x / tiles) << 4;
    int b = blockIdx.y;
    int ocb = blockIdx.z * OCPB;
    int t = threadIdx.x;
    int ocg = t >> 6;
    int pxg = t & 63, gx = pxg & 7, gy = pxg >> 3;

    const float* mski = (inslot >= 0) ? maskptr(inlvl) + (size_t)b * Hin * Hin : nullptr;
    const float* bnin = (inslot >= 0) ? g_bn2 + inslot * 384 : nullptr;

    u64 acc[2][2][8];
    #pragma unroll
    for (int py = 0; py < 2; py++)
        #pragma unroll
        for (int px = 0; px < 2; px++)
            #pragma unroll
            for (int j = 0; j < 8; j++) acc[py][px][j] = 0ull;

    const float* inb = in + (size_t)b * 192 * Hin * Hin;
    int ix0 = tx0 * STRIDE - 1, iy0 = ty0 * STRIDE - 1;

    for (int ic0 = 0; ic0 < 192; ic0 += ICB) {
        __syncthreads();
        // stage weights [icl][tap][oc]
        for (int i = t; i < ICB * 9 * OCPB; i += 256) {
            int icl = i / (9 * OCPB);
            int r = i - icl * (9 * OCPB);
            int tap = r >> 6, j = r & 63;
            s_w[i] = wt[(size_t)(ic0 + icl) * (9 * 192) + tap * 192 + ocb + j];
        }
        // stage input tile, duplicated as f32x2, with fused BN/mask/relu transform
        for (int i = t; i < ICB * IT * IT; i += 256) {
            int icl = i / (IT * IT);
            int r = i - icl * (IT * IT);
            int rr = r / IT, cc = r - rr * IT;
            int yy = iy0 + rr, xx = ix0 + cc;
            float v = 0.f;
            if ((unsigned)yy < (unsigned)Hin && (unsigned)xx < (unsigned)Hin) {
                v = inb[(size_t)(ic0 + icl) * Hin * Hin + yy * Hin + xx];
                if (inslot >= 0) {
                    int c = ic0 + icl;
                    v = (v * bnin[c] + bnin[192 + c]) * mski[yy * Hin + xx];
                    if (inrelu) v = fmaxf(v, 0.f);
                }
            }
            s_in[i] = dup2(v);
        }
        __syncthreads();
        #pragma unroll
        for (int icl = 0; icl < ICB; icl++) {
            const u64* ip = s_in + icl * IT * IT + (gy * 2 * STRIDE) * IT + gx * 2 * STRIDE;
            const float* wp = s_w + icl * 9 * OCPB + ocg * 16;
            #pragma unroll
            for (int dy = 0; dy < 3; dy++) {
                u64 r0[PSX], r1[PSX];
                #pragma unroll
                for (int c = 0; c < PSX; c++) {
                    r0[c] = ip[dy * IT + c];
                    r1[c] = ip[(STRIDE + dy) * IT + c];
                }
                #pragma unroll
                for (int dx = 0; dx < 3; dx++) {
                    const u64* wv = reinterpret_cast<const u64*>(wp + (dy * 3 + dx) * OCPB);
                    u64 w2[8];
                    #pragma unroll
                    for (int j = 0; j < 8; j++) w2[j] = wv[j];
                    #pragma unroll
                    for (int j = 0; j < 8; j++) {
                        fma2(acc[0][0][j], w2[j], r0[dx]);
                        fma2(acc[0][1][j], w2[j], r0[STRIDE + dx]);
                        fma2(acc[1][0][j], w2[j], r1[dx]);
                        fma2(acc[1][1][j], w2[j], r1[STRIDE + dx]);
                    }
                }
            }
        }
    }

    // epilogue: masked BN stats (packed) + raw output write
    int oy0 = ty0 + gy * 2, ox0 = tx0 + gx * 2;
    int HWo = Hout * Hout;
    const float* mo = maskptr(outlvl) + (size_t)b * HWo;
    float m00 = mo[oy0 * Hout + ox0], m01 = mo[oy0 * Hout + ox0 + 1];
    float m10 = mo[(oy0 + 1) * Hout + ox0], m11 = mo[(oy0 + 1) * Hout + ox0 + 1];
    u64 dm[2][2] = {{dup2(m00), dup2(m01)}, {dup2(m10), dup2(m11)}};
    u64 sum[8], ss[8];
    #pragma unroll
    for (int j = 0; j < 8; j++) {
        sum[j] = 0ull; ss[j] = 0ull;
        #pragma unroll
        for (int py = 0; py < 2; py++)
            #pragma unroll
            for (int px = 0; px < 2; px++) {
                fma2(sum[j], acc[py][px][j], dm[py][px]);
                u64 sq = mul2(acc[py][px][j], acc[py][px][j]);
                fma2(ss[j], sq, dm[py][px]);
            }
    }
    #pragma unroll
    for (int o = 16; o; o >>= 1) {
        #pragma unroll
        for (int j = 0; j < 8; j++) {
            sum[j] = add2(sum[j], __shfl_down_sync(0xffffffffu, sum[j], o));
            ss[j] = add2(ss[j], __shfl_down_sync(0xffffffffu, ss[j], o));
        }
    }
    if ((t & 31) == 0) {
        int oc0 = ocb + ocg * 16;
        #pragma unroll
        for (int j = 0; j < 8; j++) {
            float2 s = up2(sum[j]), q = up2(ss[j]);
            atomicAdd(&g_stats[oc0 + 2 * j], s.x);
            atomicAdd(&g_stats[oc0 + 2 * j + 1], s.y);
            atomicAdd(&g_stats[HD + oc0 + 2 * j], q.x);
            atomicAdd(&g_stats[HD + oc0 + 2 * j + 1], q.y);
        }
    }
    float* ob = out + ((size_t)b * 192 + ocb + ocg * 16) * HWo;
    #pragma unroll
    for (int j = 0; j < 8; j++) {
        float2 p00 = up2(acc[0][0][j]), p01 = up2(acc[0][1][j]);
        float2 p10 = up2(acc[1][0][j]), p11 = up2(acc[1][1][j]);
        float* c0 = ob + (size_t)(2 * j) * HWo + oy0 * Hout + ox0;
        float* c1 = ob + (size_t)(2 * j + 1) * HWo + oy0 * Hout + ox0;
        *(float2*)c0 = make_float2(p00.x, p01.x);
        *(float2*)(c0 + Hout) = make_float2(p10.x, p11.x);
        *(float2*)c1 = make_float2(p00.y, p01.y);
        *(float2*)(c1 + Hout) = make_float2(p10.y, p11.y);
    }
}

// ---------------- BN finalize: fold gamma/beta into per-slot scale/shift ----------------
__global__ void k_finalize(int slot, const float* __restrict__ g,
                           const float* __restrict__ bt, int lvl) {
    int c = threadIdx.x;
    float cnt = fmaxf(g_cnt[lvl], 1.f);
    float mean = g_stats[c] / cnt;
    float var = fmaxf(g_stats[HD + c] / cnt - mean * mean, 0.f);
    float inv = rsqrtf(var + BN_EPS);
    float sc = g[c] * inv;
    g_bn2[slot * 384 + c] = sc;
    g_bn2[slot * 384 + HD + c] = bt[c] - mean * sc;
}

// final apply: BN + mask + relu -> external out
__global__ void k_apply1(int srcb, int slot, int lvl, int HW, float* __restrict__ dst) {
    const float* x = bufsel(srcb);
    const float* m = maskptr(lvl);
    const float* bn = g_bn2 + slot * 384;
    int total = NB * 192 * HW;
    for (int i = blockIdx.x * blockDim.x + threadIdx.x; i < total;
         i += gridDim.x * blockDim.x) {
        int bp = i / HW;
        int c = bp % 192, b = bp / 192;
        int p = i - bp * HW;
        float v = (x[i] * bn[c] + bn[192 + c]) * m[b * HW + p];
        dst[i] = fmaxf(v, 0.f);
    }
}

// residual combine: relu( bn_a(x)*m + bn_b(idn)*m ) -> dst buffer
__global__ void k_apply2(int srcb, int sa, int idnb, int sb, int dstb, int lvl, int HW) {
    const float* x = bufsel(srcb);
    const float* idn = bufsel(idnb);
    float* dst = bufsel(dstb);
    const float* m = maskptr(lvl);
    const float* bna = g_bn2 + sa * 384;
    const float* bnb = g_bn2 + sb * 384;
    int total = NB * 192 * HW;
    for (int i = blockIdx.x * blockDim.x + threadIdx.x; i < total;
         i += gridDim.x * blockDim.x) {
        int bp = i / HW;
        int c = bp % 192, b = bp / 192;
        int p = i - bp * HW;
        float mm = m[b * HW + p];
        float v = (x[i] * bna[c] + bna[192 + c]) * mm;
        float w = (idn[i] * bnb[c] + bnb[192 + c]) * mm;
        dst[i] = fmaxf(v + w, 0.f);
    }
}

// final 1x1 conv 192->192 at res 16 (g_A -> g_Bu), fused masked stats
__global__ void k_fin(const float* __restrict__ w) {
    __shared__ float sx[192];
    int b = blockIdx.x >> 8, p = blockIdx.x & 255;
    int t = threadIdx.x;
    sx[t] = g_A[((size_t)b * 192 + t) * 256 + p];
    __syncthreads();
    const float* wr = w + t * 192;
    float s = 0.f;
    #pragma unroll 8
    for (int ic = 0; ic < 192; ic++) s += __ldg(wr + ic) * sx[ic];
    g_Bu[((size_t)b * 192 + t) * 256 + p] = s;
    float m = g_m4[b * 256 + p];
    atomicAdd(&g_stats[t], s * m);
    atomicAdd(&g_stats[HD + t], s * s * m);
}

// auxiliary outputs: mask (as float) and ids_restore
__global__ void k_aux(const int* __restrict__ mask, float* __restrict__ out) {
    int i = blockIdx.x * 256 + threadIdx.x;
    if (i < 2048) {
        out[393216 + i] = (float)mask[i];
        out[395264 + i] = (float)(i & 255);
    }
}

// ---------------- host orchestration ----------------
extern "C" void kernel_launch(void* const* d_in, const int* in_sizes, int n_in,
                              void* d_out, int out_size) {
    const float* images = (const float*)d_in[0];
    const int* mask = (const int*)d_in[1];
    const float* stem_w = (const float*)d_in[2];
    const float* stem_g = (const float*)d_in[3];
    const float* stem_b = (const float*)d_in[4];
    const float* dw1 = (const float*)d_in[5];
    const float* dg1 = (const float*)d_in[6];
    const float* db1 = (const float*)d_in[7];
    const float* dw2 = (const float*)d_in[8];
    const float* dg2 = (const float*)d_in[9];
    const float* db2 = (const float*)d_in[10];
    const float* rw1 = (const float*)d_in[11];
    const float* rg1 = (const float*)d_in[12];
    const float* rb1 = (const float*)d_in[13];
    const float* rw2 = (const float*)d_in[14];
    const float* rg2 = (const float*)d_in[15];
    const float* rb2 = (const float*)d_in[16];
    const float* fw = (const float*)d_in[17];
    const float* fg = (const float*)d_in[18];
    const float* fb = (const float*)d_in[19];
    float* out = (float*)d_out;

    // masks + counts
    k_zcnt<<<1, 32>>>();
    k_mask0<<<NB * 65536 / 256, 256>>>(mask);
    k_down<<<NB * 128 * 128 / 256, 256>>>(1, 256, 128);
    k_down<<<NB * 64 * 64 / 256, 256>>>(2, 128, 64);
    k_down<<<NB * 32 * 32 / 256, 256>>>(3, 64, 32);
    k_down<<<NB * 16 * 16 / 256, 256>>>(4, 32, 16);
    // transposed weights
    k_wt<<<8192, 256>>>(dw1, dw2, rw1, rw2);

    // stem conv (raw into A) with fused stats; finalize BN slot 0
    k_zstat<<<1, 2 * HD>>>();
    k_stem<<<NB * 192 * 65536 / 256, 256>>>(images, stem_w);
    k_finalize<<<1, 192>>>(0, stem_g, stem_b, 0);

    int Hin = 256;
    for (int i = 0; i < 4; i++) {
        int Hout = Hin / 2;
        int HW = Hout * Hout;
        int lvl = i + 1;
        int tiles = Hout / 16;
        dim3 cgrid(tiles * tiles, NB, 3);

        // d1 (stride 2): A(raw + slot-in transform) -> B raw, stats -> slot 4i+1
        k_zstat<<<1, 2 * HD>>>();
        k_conv3<2, 4><<<cgrid, 256>>>(0, 1, 4 * i + 0, Hin, Hout,
                                      (i == 0 ? 0 : -1), lvl - 1, (i == 0 ? 1 : 0), lvl);
        k_finalize<<<1, 192>>>(4 * i + 1, dg1 + i * 192, db1 + i * 192, lvl);

        // d2: B (slot d1, relu) -> C raw, stats -> slot 4i+2
        k_zstat<<<1, 2 * HD>>>();
        k_conv3<1, 8><<<cgrid, 256>>>(1, 2, 4 * i + 1, Hout, Hout,
                                      4 * i + 1, lvl, 1, lvl);
        k_finalize<<<1, 192>>>(4 * i + 2, dg2 + i * 192, db2 + i * 192, lvl);

        // r1: C (slot d2, NO relu) -> B raw, stats -> slot 4i+3
        k_zstat<<<1, 2 * HD>>>();
        k_conv3<1, 8><<<cgrid, 256>>>(2, 1, 4 * i + 2, Hout, Hout,
                                      4 * i + 2, lvl, 0, lvl);
        k_finalize<<<1, 192>>>(4 * i + 3, rg1 + i * 192, rb1 + i * 192, lvl);

        // r2: B (slot r1, relu) -> A raw, stats -> slot 4i+4
        k_zstat<<<1, 2 * HD>>>();
        k_conv3<1, 8><<<cgrid, 256>>>(1, 0, 4 * i + 3, Hout, Hout,
                                      4 * i + 3, lvl, 1, lvl);
        k_finalize<<<1, 192>>>(4 * i + 4, rg2 + i * 192, rb2 + i * 192, lvl);

        // residual combine: relu(bn_{r2}(A)*m + bn_{d2}(C)*m) -> A (materialized x)
        int blocks = std::min(8192, (NB * 192 * HW + 255) / 256);
        k_apply2<<<blocks, 256>>>(0, 4 * i + 4, 2, 4 * i + 2, 0, lvl, HW);
        Hin = Hout;
    }

    // final 1x1 proj: A@16 -> B raw (fused stats), finalize slot 17, apply -> out
    k_zstat<<<1, 2 * HD>>>();
    k_fin<<<NB * 256, 192>>>(fw);
    k_finalize<<<1, 192>>>(17, fg, fb, 4);
    k_apply1<<<1536, 256>>>(1, 17, 4, 256, out);

    // aux outputs (mask + ids_restore) if the harness expects the full tuple
    if (out_size >= 397312) k_aux<<<8, 256>>>(mask, out);
}

// round 11
// speedup vs baseline: 1.2664x; 1.0062x over previous
#include <cuda_runtime.h>
#include <algorithm>

static constexpr int NB = 8;     // batch
static constexpr int HD = 192;   // hidden dim
#define BN_EPS 1e-5f

typedef unsigned long long u64;

// ---------------- scratch (static device memory; no allocations) ----------------
__device__ float g_A[(size_t)NB * HD * 256 * 256];   // 402 MB (res-256 capable)
__device__ float g_Bu[(size_t)NB * HD * 128 * 128];  // 100 MB
__device__ float g_Cu[(size_t)NB * HD * 128 * 128];  // 100 MB
__device__ float g_m0[NB * 256 * 256];
__device__ float g_m1[NB * 128 * 128];
__device__ float g_m2[NB * 64 * 64];
__device__ float g_m3[NB * 32 * 32];
__device__ float g_m4[NB * 16 * 16];
__device__ float g_wt[16 * 192 * 9 * 192];           // transposed conv weights [conv][ic][tap][oc]
__device__ float g_stats[2 * HD];                    // per-channel sum, sumsq (reused serially)
__device__ float g_cnt[5];                           // active-site counts per level
__device__ float g_bn2[18 * 2 * HD];                 // folded BN params per instance (18 slots)

__device__ __forceinline__ float* bufsel(int i) {
    return (i == 0) ? g_A : (i == 1) ? g_Bu : g_Cu;
}
__device__ __forceinline__ float* maskptr(int lvl) {
    switch (lvl) {
        case 0: return g_m0;
        case 1: return g_m1;
        case 2: return g_m2;
        case 3: return g_m3;
        default: return g_m4;
    }
}

// ---------------- packed fp32x2 helpers (Blackwell FFMA2) ----------------
__device__ __forceinline__ void fma2(u64& d, u64 a, u64 b) {
    asm("fma.rn.f32x2 %0, %1, %2, %0;" : "+l"(d) : "l"(a), "l"(b));
}
__device__ __forceinline__ u64 mul2(u64 a, u64 b) {
    u64 d; asm("mul.rn.f32x2 %0, %1, %2;" : "=l"(d) : "l"(a), "l"(b)); return d;
}
__device__ __forceinline__ u64 add2(u64 a, u64 b) {
    u64 d; asm("add.rn.f32x2 %0, %1, %2;" : "=l"(d) : "l"(a), "l"(b)); return d;
}
__device__ __forceinline__ u64 dup2(float x) {
    unsigned int u = __float_as_uint(x);
    return (u64)u | ((u64)u << 32);
}
__device__ __forceinline__ float2 up2(u64 v) {
    float2 f;
    f.x = __uint_as_float((unsigned int)v);
    f.y = __uint_as_float((unsigned int)(v >> 32));
    return f;
}

// ---------------- small utility kernels ----------------
__global__ void k_zcnt() { if (threadIdx.x < 5) g_cnt[threadIdx.x] = 0.f; }
__global__ void k_zstat() { if (threadIdx.x < 2 * HD) g_stats[threadIdx.x] = 0.f; }

// build mask at res 256 from patch mask; accumulate active count
__global__ void k_mask0(const int* __restrict__ mask) {
    int i = blockIdx.x * 256 + threadIdx.x;
    int b = i >> 16, p = i & 65535;
    int y = p >> 8, x = p & 255;
    float v = 1.f - (float)mask[b * 256 + (y >> 4) * 16 + (x >> 4)];
    g_m0[i] = v;
    float s = v;
    for (int o = 16; o; o >>= 1) s += __shfl_down_sync(0xffffffffu, s, o);
    if ((threadIdx.x & 31) == 0) atomicAdd(&g_cnt[0], s);
}

// mask downsample: k3 s2 p1 max pool; accumulate count for output level
__global__ void k_down(int lvl, int Hin, int Hout) {
    const float* mi = maskptr(lvl - 1);
    float* mo = maskptr(lvl);
    int HW = Hout * Hout;
    int i = blockIdx.x * 256 + threadIdx.x;
    int b = i / HW, p = i - b * HW;
    int y = p / Hout, x = p - y * Hout;
    float mx = 0.f;
    #pragma unroll
    for (int dy = 0; dy < 3; dy++) {
        int yy = 2 * y - 1 + dy;
        if (yy < 0 || yy >= Hin) continue;
        #pragma unroll
        for (int dx = 0; dx < 3; dx++) {
            int xx = 2 * x - 1 + dx;
            if (xx < 0 || xx >= Hin) continue;
            mx = fmaxf(mx, mi[(b * Hin + yy) * Hin + xx]);
        }
    }
    mo[i] = mx;
    float s = mx;
    for (int o = 16; o; o >>= 1) s += __shfl_down_sync(0xffffffffu, s, o);
    if ((threadIdx.x & 31) == 0) atomicAdd(&g_cnt[lvl], s);
}

// transpose 16 conv weight tensors OIHW -> [conv][ic][tap][oc]
__global__ void k_wt(const float* __restrict__ dw1, const float* __restrict__ dw2,
                     const float* __restrict__ rw1, const float* __restrict__ rw2) {
    const size_t per = 192 * 9 * 192;
    const size_t total = 16 * per;
    for (size_t i = (size_t)blockIdx.x * blockDim.x + threadIdx.x; i < total;
         i += (size_t)gridDim.x * blockDim.x) {
        int conv = (int)(i / per);
        int r = (int)(i - (size_t)conv * per);
        int ic = r / (9 * 192);
        int r2 = r - ic * (9 * 192);
        int tap = r2 / 192, oc = r2 - tap * 192;
        int layer = conv >> 2, kind = conv & 3;
        const float* src = (kind == 0 ? dw1 : kind == 1 ? dw2 : kind == 2 ? rw1 : rw2)
                           + (size_t)layer * per;
        g_wt[i] = src[(size_t)oc * 1728 + ic * 9 + tap];
    }
}

// stem: 1x1 conv 3 -> 192 at res 256, raw output + fused masked BN stats
__global__ void k_stem(const float* __restrict__ img, const float* __restrict__ w) {
    size_t i = (size_t)blockIdx.x * 256 + threadIdx.x;
    int p = (int)(i & 65535);
    int oc = (int)((i >> 16) % 192);
    int b = (int)(i / (65536ull * 192));
    const float* ib = img + (size_t)b * 3 * 65536 + p;
    float v = w[oc * 3 + 0] * ib[0] + w[oc * 3 + 1] * ib[65536] + w[oc * 3 + 2] * ib[131072];
    g_A[i] = v;
    float m = g_m0[b * 65536 + p];
    float s = v * m, q = v * v * m;
    for (int o = 16; o; o >>= 1) {
        s += __shfl_down_sync(0xffffffffu, s, o);
        q += __shfl_down_sync(0xffffffffu, q, o);
    }
    __shared__ float sh[8][2];
    int wrp = threadIdx.x >> 5, ln = threadIdx.x & 31;
    if (ln == 0) { sh[wrp][0] = s; sh[wrp][1] = q; }
    __syncthreads();
    if (threadIdx.x == 0) {
        float a = 0.f, b2 = 0.f;
        #pragma unroll
        for (int k = 0; k < 8; k++) { a += sh[k][0]; b2 += sh[k][1]; }
        atomicAdd(&g_stats[oc], a);
        atomicAdd(&g_stats[HD + oc], b2);
    }
}

// ================= 3x3 conv 192->192, register-tiled, dup'd-smem, fused =================
// block: 16x16 output px, 64 oc slice (blockIdx.z); 256 threads = 64 px-groups(2x2) x 4 oc-groups(16 oc)
// staging applies BN(inslot)+mask+optional relu of the INPUT tensor;
// epilogue writes raw conv output + accumulates masked BN stats into g_stats.
template <int STRIDE, int ICB>
__global__ void __launch_bounds__(256, 2)
k_conv3(int srcb, int dstb, int wslot, int Hin, int Hout,
        int inslot, int inlvl, int inrelu, int outlvl) {
    constexpr int IT = 15 * STRIDE + 3;   // stride1:18, stride2:33
    constexpr int OCPB = 64;
    constexpr int PSX = STRIDE + 3;

    __shared__ __align__(16) u64 s_in[ICB * IT * IT];
    __shared__ __align__(16) float s_w[ICB * 9 * OCPB];

    const float* in = bufsel(srcb);
    float* out = bufsel(dstb);
    const float* wt = g_wt + (size_t)wslot * (192 * 9 * 192);

    int tiles = Hout >> 4;
    int tx0 = (blockIdx.x % tiles) << 4;
    int ty0 = (blockIdx.x / tiles) << 4;
    int b = blockIdx.y;
    int ocb = blockIdx.z * OCPB;
    int t = threadIdx.x;
    int ocg = t >> 6;
    int pxg = t & 63, gx = pxg & 7, gy = pxg >> 3;

    const float* mski = (inslot >= 0) ? maskptr(inlvl) + (size_t)b * Hin * Hin : nullptr;
    const float* bnin = (inslot >= 0) ? g_bn2 + inslot * 384 : nullptr;

    u64 acc[2][2][8];
    #pragma unroll
    for (int py = 0; py < 2; py++)
        #pragma unroll
        for (int px = 0; px < 2; px++)
            #pragma unroll
            for (int j = 0; j < 8; j++) acc[py][px][j] = 0ull;

    const float* inb = in + (size_t)b * 192 * Hin * Hin;
    int ix0 = tx0 * STRIDE - 1, iy0 = ty0 * STRIDE - 1;

    for (int ic0 = 0; ic0 < 192; ic0 += ICB) {
        __syncthreads();
        // stage weights [icl][tap][oc]
        for (int i = t; i < ICB * 9 * OCPB; i += 256) {
            int icl = i / (9 * OCPB);
            int r = i - icl * (9 * OCPB);
            int tap = r >> 6, j = r & 63;
            s_w[i] = wt[(size_t)(ic0 + icl) * (9 * 192) + tap * 192 + ocb + j];
        }
        // stage input tile, duplicated as f32x2, with fused BN/mask/relu transform
        for (int i = t; i < ICB * IT * IT; i += 256) {
            int icl = i / (IT * IT);
            int r = i - icl * (IT * IT);
            int rr = r / IT, cc = r - rr * IT;
            int yy = iy0 + rr, xx = ix0 + cc;
            float v = 0.f;
            if ((unsigned)yy < (unsigned)Hin && (unsigned)xx < (unsigned)Hin) {
                v = inb[(size_t)(ic0 + icl) * Hin * Hin + yy * Hin + xx];
                if (inslot >= 0) {
                    int c = ic0 + icl;
                    v = (v * bnin[c] + bnin[192 + c]) * mski[yy * Hin + xx];
                    if (inrelu) v = fmaxf(v, 0.f);
                }
            }
            s_in[i] = dup2(v);
        }
        __syncthreads();
        #pragma unroll
        for (int icl = 0; icl < ICB; icl++) {
            const u64* ip = s_in + icl * IT * IT + (gy * 2 * STRIDE) * IT + gx * 2 * STRIDE;
            const float* wp = s_w + icl * 9 * OCPB + ocg * 16;
            #pragma unroll
            for (int dy = 0; dy < 3; dy++) {
                u64 r0[PSX], r1[PSX];
                #pragma unroll
                for (int c = 0; c < PSX; c++) {
                    r0[c] = ip[dy * IT + c];
                    r1[c] = ip[(STRIDE + dy) * IT + c];
                }
                #pragma unroll
                for (int dx = 0; dx < 3; dx++) {
                    const u64* wv = reinterpret_cast<const u64*>(wp + (dy * 3 + dx) * OCPB);
                    u64 w2[8];
                    #pragma unroll
                    for (int j = 0; j < 8; j++) w2[j] = wv[j];
                    #pragma unroll
                    for (int j = 0; j < 8; j++) {
                        fma2(acc[0][0][j], w2[j], r0[dx]);
                        fma2(acc[0][1][j], w2[j], r0[STRIDE + dx]);
                        fma2(acc[1][0][j], w2[j], r1[dx]);
                        fma2(acc[1][1][j], w2[j], r1[STRIDE + dx]);
                    }
                }
            }
        }
    }

    // epilogue: masked BN stats (packed) + raw output write
    int oy0 = ty0 + gy * 2, ox0 = tx0 + gx * 2;
    int HWo = Hout * Hout;
    const float* mo = maskptr(outlvl) + (size_t)b * HWo;
    float m00 = mo[oy0 * Hout + ox0], m01 = mo[oy0 * Hout + ox0 + 1];
    float m10 = mo[(oy0 + 1) * Hout + ox0], m11 = mo[(oy0 + 1) * Hout + ox0 + 1];
    u64 dm[2][2] = {{dup2(m00), dup2(m01)}, {dup2(m10), dup2(m11)}};
    u64 sum[8], ss[8];
    #pragma unroll
    for (int j = 0; j < 8; j++) {
        sum[j] = 0ull; ss[j] = 0ull;
        #pragma unroll
        for (int py = 0; py < 2; py++)
            #pragma unroll
            for (int px = 0; px < 2; px++) {
                fma2(sum[j], acc[py][px][j], dm[py][px]);
                u64 sq = mul2(acc[py][px][j], acc[py][px][j]);
                fma2(ss[j], sq, dm[py][px]);
            }
    }
    #pragma unroll
    for (int o = 16; o; o >>= 1) {
        #pragma unroll
        for (int j = 0; j < 8; j++) {
            sum[j] = add2(sum[j], __shfl_down_sync(0xffffffffu, sum[j], o));
            ss[j] = add2(ss[j], __shfl_down_sync(0xffffffffu, ss[j], o));
        }
    }
    if ((t & 31) == 0) {
        int oc0 = ocb + ocg * 16;
        #pragma unroll
        for (int j = 0; j < 8; j++) {
            float2 s = up2(sum[j]), q = up2(ss[j]);
            atomicAdd(&g_stats[oc0 + 2 * j], s.x);
            atomicAdd(&g_stats[oc0 + 2 * j + 1], s.y);
            atomicAdd(&g_stats[HD + oc0 + 2 * j], q.x);
            atomicAdd(&g_stats[HD + oc0 + 2 * j + 1], q.y);
        }
    }
    float* ob = out + ((size_t)b * 192 + ocb + ocg * 16) * HWo;
    #pragma unroll
    for (int j = 0; j < 8; j++) {
        float2 p00 = up2(acc[0][0][j]), p01 = up2(acc[0][1][j]);
        float2 p10 = up2(acc[1][0][j]), p11 = up2(acc[1][1][j]);
        float* c0 = ob + (size_t)(2 * j) * HWo + oy0 * Hout + ox0;
        float* c1 = ob + (size_t)(2 * j + 1) * HWo + oy0 * Hout + ox0;
        *(float2*)c0 = make_float2(p00.x, p01.x);
        *(float2*)(c0 + Hout) = make_float2(p10.x, p11.x);
        *(float2*)c1 = make_float2(p00.y, p01.y);
        *(float2*)(c1 + Hout) = make_float2(p10.y, p11.y);
    }
}

// ---------------- BN finalize: fold gamma/beta into per-slot scale/shift ----------------
__global__ void k_finalize(int slot, const float* __restrict__ g,
                           const float* __restrict__ bt, int lvl) {
    int c = threadIdx.x;
    float cnt = fmaxf(g_cnt[lvl], 1.f);
    float mean = g_stats[c] / cnt;
    float var = fmaxf(g_stats[HD + c] / cnt - mean * mean, 0.f);
    float inv = rsqrtf(var + BN_EPS);
    float sc = g[c] * inv;
    g_bn2[slot * 384 + c] = sc;
    g_bn2[slot * 384 + HD + c] = bt[c] - mean * sc;
}

// final apply: BN + mask + relu -> external out
__global__ void k_apply1(int srcb, int slot, int lvl, int HW, float* __restrict__ dst) {
    const float* x = bufsel(srcb);
    const float* m = maskptr(lvl);
    const float* bn = g_bn2 + slot * 384;
    int total = NB * 192 * HW;
    for (int i = blockIdx.x * blockDim.x + threadIdx.x; i < total;
         i += gridDim.x * blockDim.x) {
        int bp = i / HW;
        int c = bp % 192, b = bp / 192;
        int p = i - bp * HW;
        float v = (x[i] * bn[c] + bn[192 + c]) * m[b * HW + p];
        dst[i] = fmaxf(v, 0.f);
    }
}

// residual combine: relu( bn_a(x)*m + bn_b(idn)*m ) -> dst buffer
__global__ void k_apply2(int srcb, int sa, int idnb, int sb, int dstb, int lvl, int HW) {
    const float* x = bufsel(srcb);
    const float* idn = bufsel(idnb);
    float* dst = bufsel(dstb);
    const float* m = maskptr(lvl);
    const float* bna = g_bn2 + sa * 384;
    const float* bnb = g_bn2 + sb * 384;
    int total = NB * 192 * HW;
    for (int i = blockIdx.x * blockDim.x + threadIdx.x; i < total;
         i += gridDim.x * blockDim.x) {
        int bp = i / HW;
        int c = bp % 192, b = bp / 192;
        int p = i - bp * HW;
        float mm = m[b * HW + p];
        float v = (x[i] * bna[c] + bna[192 + c]) * mm;
        float w = (idn[i] * bnb[c] + bnb[192 + c]) * mm;
        dst[i] = fmaxf(v + w, 0.f);
    }
}

// final 1x1 conv 192->192 at res 16 (g_A -> g_Bu), fused masked stats
__global__ void k_fin(const float* __restrict__ w) {
    __shared__ float sx[192];
    int b = blockIdx.x >> 8, p = blockIdx.x & 255;
    int t = threadIdx.x;
    sx[t] = g_A[((size_t)b * 192 + t) * 256 + p];
    __syncthreads();
    const float* wr = w + t * 192;
    float s = 0.f;
    #pragma unroll 8
    for (int ic = 0; ic < 192; ic++) s += __ldg(wr + ic) * sx[ic];
    g_Bu[((size_t)b * 192 + t) * 256 + p] = s;
    float m = g_m4[b * 256 + p];
    atomicAdd(&g_stats[t], s * m);
    atomicAdd(&g_stats[HD + t], s * s * m);
}

// auxiliary outputs: mask (as float) and ids_restore
__global__ void k_aux(const int* __restrict__ mask, float* __restrict__ out) {
    int i = blockIdx.x * 256 + threadIdx.x;
    if (i < 2048) {
        out[393216 + i] = (float)mask[i];
        out[395264 + i] = (float)(i & 255);
    }
}

// ---------------- host orchestration ----------------
extern "C" void kernel_launch(void* const* d_in, const int* in_sizes, int n_in,
                              void* d_out, int out_size) {
    const float* images = (const float*)d_in[0];
    const int* mask = (const int*)d_in[1];
    const float* stem_w = (const float*)d_in[2];
    const float* stem_g = (const float*)d_in[3];
    const float* stem_b = (const float*)d_in[4];
    const float* dw1 = (const float*)d_in[5];
    const float* dg1 = (const float*)d_in[6];
    const float* db1 = (const float*)d_in[7];
    const float* dw2 = (const float*)d_in[8];
    const float* dg2 = (const float*)d_in[9];
    const float* db2 = (const float*)d_in[10];
    const float* rw1 = (const float*)d_in[11];
    const float* rg1 = (const float*)d_in[12];
    const float* rb1 = (const float*)d_in[13];
    const float* rw2 = (const float*)d_in[14];
    const float* rg2 = (const float*)d_in[15];
    const float* rb2 = (const float*)d_in[16];
    const float* fw = (const float*)d_in[17];
    const float* fg = (const float*)d_in[18];
    const float* fb = (const float*)d_in[19];
    float* out = (float*)d_out;

    // masks + counts
    k_zcnt<<<1, 32>>>();
    k_mask0<<<NB * 65536 / 256, 256>>>(mask);
    k_down<<<NB * 128 * 128 / 256, 256>>>(1, 256, 128);
    k_down<<<NB * 64 * 64 / 256, 256>>>(2, 128, 64);
    k_down<<<NB * 32 * 32 / 256, 256>>>(3, 64, 32);
    k_down<<<NB * 16 * 16 / 256, 256>>>(4, 32, 16);
    // transposed weights
    k_wt<<<8192, 256>>>(dw1, dw2, rw1, rw2);

    // stem conv (raw into A) with fused stats; finalize BN slot 0
    k_zstat<<<1, 2 * HD>>>();
    k_stem<<<NB * 192 * 65536 / 256, 256>>>(images, stem_w);
    k_finalize<<<1, 192>>>(0, stem_g, stem_b, 0);

    int Hin = 256;
    for (int i = 0; i < 4; i++) {
        int Hout = Hin / 2;
        int HW = Hout * Hout;
        int lvl = i + 1;
        int tiles = Hout / 16;
        dim3 cgrid(tiles * tiles, NB, 3);

        // d1 (stride 2): A(raw + slot-in transform) -> B raw, stats -> slot 4i+1
        k_zstat<<<1, 2 * HD>>>();
        k_conv3<2, 4><<<cgrid, 256>>>(0, 1, 4 * i + 0, Hin, Hout,
                                      (i == 0 ? 0 : -1), lvl - 1, (i == 0 ? 1 : 0), lvl);
        k_finalize<<<1, 192>>>(4 * i + 1, dg1 + i * 192, db1 + i * 192, lvl);

        // d2: B (slot d1, relu) -> C raw, stats -> slot 4i+2
        k_zstat<<<1, 2 * HD>>>();
        k_conv3<1, 8><<<cgrid, 256>>>(1, 2, 4 * i + 1, Hout, Hout,
                                      4 * i + 1, lvl, 1, lvl);
        k_finalize<<<1, 192>>>(4 * i + 2, dg2 + i * 192, db2 + i * 192, lvl);

        // r1: C (slot d2, NO relu) -> B raw, stats -> slot 4i+3
        k_zstat<<<1, 2 * HD>>>();
        k_conv3<1, 8><<<cgrid, 256>>>(2, 1, 4 * i + 2, Hout, Hout,
                                      4 * i + 2, lvl, 0, lvl);
        k_finalize<<<1, 192>>>(4 * i + 3, rg1 + i * 192, rb1 + i * 192, lvl);

        // r2: B (slot r1, relu) -> A raw, stats -> slot 4i+4
        k_zstat<<<1, 2 * HD>>>();
        k_conv3<1, 8><<<cgrid, 256>>>(1, 0, 4 * i + 3, Hout, Hout,
                                      4 * i + 3, lvl, 1, lvl);
        k_finalize<<<1, 192>>>(4 * i + 4, rg2 + i * 192, rb2 + i * 192, lvl);

        // residual combine: relu(bn_{r2}(A)*m + bn_{d2}(C)*m) -> A (materialized x)
        int blocks = std::min(8192, (NB * 192 * HW + 255) / 256);
        k_apply2<<<blocks, 256>>>(0, 4 * i + 4, 2, 4 * i + 2, 0, lvl, HW);
        Hin = Hout;
    }

    // final 1x1 proj: A@16 -> B raw (fused stats), finalize slot 17, apply -> out
    k_zstat<<<1, 2 * HD>>>();
    k_fin<<<NB * 256, 192>>>(fw);
    k_finalize<<<1, 192>>>(17, fg, fb, 4);
    k_apply1<<<1536, 256>>>(1, 17, 4, 256, out);

    // aux outputs (mask + ids_restore) if the harness expects the full tuple
    if (out_size >= 397312) k_aux<<<8, 256>>>(mask, out);
}